// round 1
// baseline (speedup 1.0000x reference)
#include <cuda_runtime.h>
#include <cstdint>

#define BB 256
#define DD 131072
#define NSPLIT 128
#define KSLAB (DD / NSPLIT)   // 1024
#define BKG 16
#define BMG 128

// Static device scratch (no allocations allowed)
__device__ double g_rowsum[BB];
__device__ double g_rowsumsq[BB];
__device__ unsigned long long g_rowmask[BB];
__device__ float g_part[NSPLIT * 3 * BMG * BMG];   // 24 MB partial Gram slabs
__device__ float g_G[BB * BB];
__device__ float g_p;
__device__ float g_scale;

// ---------------------------------------------------------------------------
// Kernel 1: per-row sum, sum of squares (fp64), presence bitmap of rintf(x)
// One block per row, 256 threads.
// ---------------------------------------------------------------------------
__global__ void stats_kernel(const float* __restrict__ x) {
    int row = blockIdx.x;
    int t = threadIdx.x;
    const float4* xr = reinterpret_cast<const float4*>(x + (size_t)row * DD);

    double s = 0.0, q = 0.0;
    unsigned long long mask = 0ull;

    for (int i = t; i < DD / 4; i += 256) {
        float4 v = xr[i];
        s += (double)v.x + (double)v.y + (double)v.z + (double)v.w;
        q += (double)v.x * v.x + (double)v.y * v.y
           + (double)v.z * v.z + (double)v.w * v.w;
        int b;
        b = (int)rintf(v.x) + 32; b = b < 0 ? 0 : (b > 63 ? 63 : b); mask |= 1ull << b;
        b = (int)rintf(v.y) + 32; b = b < 0 ? 0 : (b > 63 ? 63 : b); mask |= 1ull << b;
        b = (int)rintf(v.z) + 32; b = b < 0 ? 0 : (b > 63 ? 63 : b); mask |= 1ull << b;
        b = (int)rintf(v.w) + 32; b = b < 0 ? 0 : (b > 63 ? 63 : b); mask |= 1ull << b;
    }

    __shared__ double ssum[256];
    __shared__ double ssq[256];
    __shared__ unsigned long long smask[256];
    ssum[t] = s; ssq[t] = q; smask[t] = mask;
    __syncthreads();
    for (int st = 128; st > 0; st >>= 1) {
        if (t < st) {
            ssum[t] += ssum[t + st];
            ssq[t]  += ssq[t + st];
            smask[t] |= smask[t + st];
        }
        __syncthreads();
    }
    if (t == 0) {
        g_rowsum[row]   = ssum[0];
        g_rowsumsq[row] = ssq[0];
        g_rowmask[row]  = smask[0];
    }
}

// ---------------------------------------------------------------------------
// Kernel 2: Gram partials. G = X @ X^T, symmetric -> 3 tiles of 128x128.
// grid = (3 tiles, NSPLIT k-splits), block = 256 threads, 8x8 per-thread tile.
// Each CTA writes its own partial slab (no atomics -> deterministic).
// ---------------------------------------------------------------------------
__global__ void gram_kernel(const float* __restrict__ x) {
    int tile  = blockIdx.x;          // 0:(0,0) 1:(1,0) 2:(1,1)
    int split = blockIdx.y;
    int bi = (tile == 0) ? 0 : 1;
    int bj = (tile == 2) ? 1 : 0;

    const float* Ag = x + (size_t)(bi * 128) * DD + (size_t)split * KSLAB;
    const float* Bg = x + (size_t)(bj * 128) * DD + (size_t)split * KSLAB;

    __shared__ float As[BKG][BMG + 4];
    __shared__ float Bs[BKG][BMG + 4];

    int t  = threadIdx.x;
    int tx = t & 15;
    int ty = t >> 4;

    float acc[8][8];
    #pragma unroll
    for (int m = 0; m < 8; m++)
        #pragma unroll
        for (int n = 0; n < 8; n++) acc[m][n] = 0.f;

    for (int k0 = 0; k0 < KSLAB; k0 += BKG) {
        #pragma unroll
        for (int i = 0; i < 2; i++) {
            int v   = t + i * 256;        // 0..511
            int row = v >> 2;             // 4 float4 per row (BKG=16)
            int kk  = (v & 3) * 4;
            float4 a = *reinterpret_cast<const float4*>(Ag + (size_t)row * DD + k0 + kk);
            As[kk + 0][row] = a.x; As[kk + 1][row] = a.y;
            As[kk + 2][row] = a.z; As[kk + 3][row] = a.w;
            float4 b = *reinterpret_cast<const float4*>(Bg + (size_t)row * DD + k0 + kk);
            Bs[kk + 0][row] = b.x; Bs[kk + 1][row] = b.y;
            Bs[kk + 2][row] = b.z; Bs[kk + 3][row] = b.w;
        }
        __syncthreads();

        #pragma unroll
        for (int kk = 0; kk < BKG; kk++) {
            float a[8], b[8];
            #pragma unroll
            for (int m = 0; m < 8; m++) a[m] = As[kk][ty * 8 + m];
            #pragma unroll
            for (int n = 0; n < 8; n++) b[n] = Bs[kk][tx * 8 + n];
            #pragma unroll
            for (int m = 0; m < 8; m++)
                #pragma unroll
                for (int n = 0; n < 8; n++)
                    acc[m][n] += a[m] * b[n];
        }
        __syncthreads();
    }

    float* P = g_part + ((size_t)split * 3 + tile) * BMG * BMG;
    #pragma unroll
    for (int m = 0; m < 8; m++)
        #pragma unroll
        for (int n = 0; n < 8; n++)
            P[(ty * 8 + m) * BMG + (tx * 8 + n)] = acc[m][n];
}

// ---------------------------------------------------------------------------
// Kernel 3: deterministic fp64 reduction of partials into g_G (full 256x256,
// mirroring the (0,1) block from tile 1). grid = 256 blocks (i), 256 thr (j).
// ---------------------------------------------------------------------------
__global__ void reduce_kernel() {
    int i = blockIdx.x;
    int j = threadIdx.x;

    int tile, r, c;
    if (i < 128 && j < 128)        { tile = 0; r = i;       c = j; }
    else if (i >= 128 && j < 128)  { tile = 1; r = i - 128; c = j; }
    else if (i >= 128 && j >= 128) { tile = 2; r = i - 128; c = j - 128; }
    else                            { tile = 1; r = j - 128; c = i; }  // mirror

    double sum = 0.0;
    const float* base = g_part + (size_t)tile * BMG * BMG + r * BMG + c;
    for (int s = 0; s < NSPLIT; s++)
        sum += (double)base[(size_t)s * 3 * BMG * BMG];

    g_G[i * BB + j] = (float)sum;
}

// ---------------------------------------------------------------------------
// Kernel 4: finalize scalar p. Single block, thread i = row i.
// ---------------------------------------------------------------------------
__global__ void finalize_kernel() {
    int i = threadIdx.x;
    __shared__ double sh_s[BB];
    __shared__ double sh_std[BB];
    __shared__ double red[BB];
    __shared__ unsigned long long shm[BB];

    double s = g_rowsum[i];
    double q = g_rowsumsq[i];
    unsigned long long mymask = g_rowmask[i];

    const double dD  = (double)DD;
    const double inv = 1.0 / (dD - 1.0);

    double covii = (q - s * s / dD) * inv;
    sh_s[i]   = s;
    sh_std[i] = sqrt(covii);
    shm[i]    = mymask;
    __syncthreads();

    // global unique: OR-reduce of row masks
    for (int st = 128; st > 0; st >>= 1) {
        if (i < st) shm[i] |= shm[i + st];
        __syncthreads();
    }
    int total_u = __popcll(shm[0]);
    int row_u   = __popcll(mymask);

    // per-row: sum |clip(corr)| and Gram row sum (exact diagonal q)
    double sumAbs = 0.0, G1 = 0.0;
    const float* Gi = g_G + i * BB;
    double stdi = sh_std[i];
    for (int j = 0; j < BB; j++) {
        double Gij = (j == i) ? q : (double)Gi[j];
        G1 += Gij;
        double cov = (Gij - s * sh_s[j] / dD) * inv;
        double c = cov / (stdi * sh_std[j]);
        c = fabs(c);
        if (c > 1.0) c = 1.0;
        sumAbs += c;
    }
    double factor1 = sumAbs / (double)BB;

    // S = sum_ij G
    red[i] = G1; __syncthreads();
    for (int st = 128; st > 0; st >>= 1) {
        if (i < st) red[i] += red[i + st];
        __syncthreads();
    }
    double S = red[0];
    __syncthreads();

    // row_mse via Gram identity
    const double dB = (double)BB;
    double mseD    = q - (2.0 / dB) * G1 + S / (dB * dB);
    double row_mse = mseD / dD;

    red[i] = row_mse; __syncthreads();
    for (int st = 128; st > 0; st >>= 1) {
        if (i < st) red[i] += red[i + st];
        __syncthreads();
    }
    double total_mse = red[0];
    __syncthreads();

    double f2   = row_mse / total_mse;
    double f3   = (double)row_u / (double)total_u;
    double cand = (1.0 - factor1) * f2 * f3;

    red[i] = cand; __syncthreads();
    for (int st = 128; st > 0; st >>= 1) {
        if (i < st) red[i] = fmax(red[i], red[i + st]);
        __syncthreads();
    }
    if (i == 0) {
        double p = fmax(red[0], 0.0);
        float pf = (float)p;
        g_p = pf;
        g_scale = 1.0f / (1.0f - pf);
    }
}

// ---------------------------------------------------------------------------
// Kernel 5: dropout. out = x * (noise >= p) / (1-p)
// ---------------------------------------------------------------------------
__global__ void dropout_kernel(const float* __restrict__ x,
                               const float* __restrict__ noise,
                               float* __restrict__ out) {
    float p  = g_p;
    float sc = g_scale;
    int idx = blockIdx.x * blockDim.x + threadIdx.x;
    const int n4 = BB * DD / 4;
    if (idx < n4) {
        float4 v = reinterpret_cast<const float4*>(x)[idx];
        float4 nz = reinterpret_cast<const float4*>(noise)[idx];
        float4 o;
        o.x = (nz.x >= p) ? v.x * sc : 0.f;
        o.y = (nz.y >= p) ? v.y * sc : 0.f;
        o.z = (nz.z >= p) ? v.z * sc : 0.f;
        o.w = (nz.w >= p) ? v.w * sc : 0.f;
        reinterpret_cast<float4*>(out)[idx] = o;
    }
}

extern "C" void kernel_launch(void* const* d_in, const int* in_sizes, int n_in,
                              void* d_out, int out_size) {
    const float* x     = (const float*)d_in[0];
    const float* noise = (const float*)d_in[1];
    float* out = (float*)d_out;

    stats_kernel<<<BB, 256>>>(x);
    gram_kernel<<<dim3(3, NSPLIT), 256>>>(x);
    reduce_kernel<<<BB, 256>>>();
    finalize_kernel<<<1, BB>>>();
    const int n4 = BB * DD / 4;
    dropout_kernel<<<(n4 + 255) / 256, 256>>>(x, noise, out);
}

// round 2
// speedup vs baseline: 1.3783x; 1.3783x over previous
#include <cuda_runtime.h>
#include <cstdint>

#define BB 256
#define DD 131072
#define NSPLIT 128
#define KSLAB (DD / NSPLIT)   // 1024
#define BKG 16
#define BMG 128

// Static device scratch (no allocations allowed)
__device__ double g_rowsum[BB];
__device__ double g_rowsumsq[BB];
__device__ double g_std[BB];
__device__ unsigned long long g_rowmask[BB];
__device__ double g_f1[BB];
__device__ double g_G1[BB];
__device__ float g_part[NSPLIT * 3 * BMG * BMG];   // 24 MB partial Gram slabs
__device__ float g_G[BB * BB];
__device__ float g_p;
__device__ float g_scale;

__device__ __forceinline__ unsigned long long dup2(float f) {
    unsigned int u = __float_as_uint(f);
    return ((unsigned long long)u << 32) | (unsigned long long)u;
}

__device__ __forceinline__ void ffma2(unsigned long long& d,
                                      unsigned long long a,
                                      unsigned long long b) {
    asm("fma.rn.f32x2 %0, %1, %2, %3;" : "=l"(d) : "l"(a), "l"(b), "l"(d));
}

// ---------------------------------------------------------------------------
// Kernel 1: per-row sum, sum of squares (fp64), presence bitmap of rintf(x),
// and row std. One block per row, 256 threads.
// ---------------------------------------------------------------------------
__global__ void stats_kernel(const float* __restrict__ x) {
    int row = blockIdx.x;
    int t = threadIdx.x;
    const float4* xr = reinterpret_cast<const float4*>(x + (size_t)row * DD);

    double s = 0.0, q = 0.0;
    unsigned long long mask = 0ull;

    for (int i = t; i < DD / 4; i += 256) {
        float4 v = xr[i];
        s += (double)v.x + (double)v.y + (double)v.z + (double)v.w;
        q += (double)v.x * v.x + (double)v.y * v.y
           + (double)v.z * v.z + (double)v.w * v.w;
        int b;
        b = (int)rintf(v.x) + 32; b = b < 0 ? 0 : (b > 63 ? 63 : b); mask |= 1ull << b;
        b = (int)rintf(v.y) + 32; b = b < 0 ? 0 : (b > 63 ? 63 : b); mask |= 1ull << b;
        b = (int)rintf(v.z) + 32; b = b < 0 ? 0 : (b > 63 ? 63 : b); mask |= 1ull << b;
        b = (int)rintf(v.w) + 32; b = b < 0 ? 0 : (b > 63 ? 63 : b); mask |= 1ull << b;
    }

    __shared__ double ssum[256];
    __shared__ double ssq[256];
    __shared__ unsigned long long smask[256];
    ssum[t] = s; ssq[t] = q; smask[t] = mask;
    __syncthreads();
    for (int st = 128; st > 0; st >>= 1) {
        if (t < st) {
            ssum[t] += ssum[t + st];
            ssq[t]  += ssq[t + st];
            smask[t] |= smask[t + st];
        }
        __syncthreads();
    }
    if (t == 0) {
        double S = ssum[0], Q = ssq[0];
        g_rowsum[row]   = S;
        g_rowsumsq[row] = Q;
        g_rowmask[row]  = smask[0];
        const double dD = (double)DD;
        g_std[row] = sqrt((Q - S * S / dD) / (dD - 1.0));
    }
}

// ---------------------------------------------------------------------------
// Kernel 2: Gram partials with packed f32x2 FMA.
// G = X @ X^T, symmetric -> 3 tiles of 128x128.
// grid = (3 tiles, NSPLIT k-splits), block = 256 threads.
// Per-thread tile: rows {ty*4+r, 64+ty*4+r} x cols {tx*4+c, 64+tx*4+c}
// (conflict-free 256B-contiguous fragment reads).
// A is stored in SMEM as duplicated f32x2 pairs; accs are f32x2 pairs over n.
// ---------------------------------------------------------------------------
__global__ void gram_kernel(const float* __restrict__ x) {
    int tile  = blockIdx.x;          // 0:(0,0) 1:(1,0) 2:(1,1)
    int split = blockIdx.y;
    int bi = (tile == 0) ? 0 : 1;
    int bj = (tile == 2) ? 1 : 0;

    const float* Ag = x + (size_t)(bi * 128) * DD + (size_t)split * KSLAB;
    const float* Bg = x + (size_t)(bj * 128) * DD + (size_t)split * KSLAB;

    __shared__ unsigned long long As2[BKG][BMG];  // duplicated pairs, 16 KB
    __shared__ float Bs[BKG][BMG + 4];            // ~8.4 KB

    int t  = threadIdx.x;
    int tx = t & 15;
    int ty = t >> 4;

    unsigned long long acc2[8][4];
    #pragma unroll
    for (int m = 0; m < 8; m++)
        #pragma unroll
        for (int n2 = 0; n2 < 4; n2++) acc2[m][n2] = 0ull;

    for (int k0 = 0; k0 < KSLAB; k0 += BKG) {
        #pragma unroll
        for (int i = 0; i < 2; i++) {
            int v   = t + i * 256;        // 0..511
            int row = v >> 2;             // 4 float4 per row (BKG=16)
            int kk  = (v & 3) * 4;
            float4 a = *reinterpret_cast<const float4*>(Ag + (size_t)row * DD + k0 + kk);
            As2[kk + 0][row] = dup2(a.x); As2[kk + 1][row] = dup2(a.y);
            As2[kk + 2][row] = dup2(a.z); As2[kk + 3][row] = dup2(a.w);
            float4 b = *reinterpret_cast<const float4*>(Bg + (size_t)row * DD + k0 + kk);
            Bs[kk + 0][row] = b.x; Bs[kk + 1][row] = b.y;
            Bs[kk + 2][row] = b.z; Bs[kk + 3][row] = b.w;
        }
        __syncthreads();

        #pragma unroll
        for (int kk = 0; kk < BKG; kk++) {
            unsigned long long a2[8];
            #pragma unroll
            for (int r = 0; r < 4; r++) {
                a2[r]     = As2[kk][ty * 4 + r];
                a2[4 + r] = As2[kk][64 + ty * 4 + r];
            }
            unsigned long long b2[4];
            const unsigned long long* bp0 =
                reinterpret_cast<const unsigned long long*>(&Bs[kk][tx * 4]);
            const unsigned long long* bp1 =
                reinterpret_cast<const unsigned long long*>(&Bs[kk][64 + tx * 4]);
            b2[0] = bp0[0]; b2[1] = bp0[1];
            b2[2] = bp1[0]; b2[3] = bp1[1];

            #pragma unroll
            for (int m = 0; m < 8; m++)
                #pragma unroll
                for (int n2 = 0; n2 < 4; n2++)
                    ffma2(acc2[m][n2], a2[m], b2[n2]);
        }
        __syncthreads();
    }

    float* P = g_part + ((size_t)split * 3 + tile) * BMG * BMG;
    #pragma unroll
    for (int m = 0; m < 8; m++) {
        int mg = (m < 4) ? (ty * 4 + m) : (64 + ty * 4 + (m - 4));
        #pragma unroll
        for (int n2 = 0; n2 < 4; n2++) {
            int ng = (n2 < 2) ? (tx * 4 + n2 * 2) : (64 + tx * 4 + (n2 - 2) * 2);
            unsigned long long v = acc2[m][n2];
            P[mg * BMG + ng]     = __uint_as_float((unsigned int)(v & 0xffffffffull));
            P[mg * BMG + ng + 1] = __uint_as_float((unsigned int)(v >> 32));
        }
    }
}

// ---------------------------------------------------------------------------
// Kernel 3: deterministic fp64 reduction of partials into g_G (full 256x256,
// mirroring the (0,1) block from tile 1). grid = 256 blocks (i), 256 thr (j).
// ---------------------------------------------------------------------------
__global__ void reduce_kernel() {
    int i = blockIdx.x;
    int j = threadIdx.x;

    int tile, r, c;
    if (i < 128 && j < 128)        { tile = 0; r = i;       c = j; }
    else if (i >= 128 && j < 128)  { tile = 1; r = i - 128; c = j; }
    else if (i >= 128 && j >= 128) { tile = 2; r = i - 128; c = j - 128; }
    else                            { tile = 1; r = j - 128; c = i; }  // mirror

    double sum = 0.0;
    const float* base = g_part + (size_t)tile * BMG * BMG + r * BMG + c;
    for (int s = 0; s < NSPLIT; s++)
        sum += (double)base[(size_t)s * 3 * BMG * BMG];

    g_G[i * BB + j] = (float)sum;
}

// ---------------------------------------------------------------------------
// Kernel 4: per-row pass. Block i, thread j: sum_j |clip(corr_ij)| and
// (G row_i) . 1 in fp64 shared reductions.
// ---------------------------------------------------------------------------
__global__ void rowpass_kernel() {
    int i = blockIdx.x;
    int j = threadIdx.x;
    __shared__ double redA[BB];
    __shared__ double redG[BB];

    const double dD  = (double)DD;
    const double inv = 1.0 / (dD - 1.0);

    double s_i = g_rowsum[i];
    double s_j = g_rowsum[j];
    double Gij = (j == i) ? g_rowsumsq[i] : (double)g_G[i * BB + j];

    double cov = (Gij - s_i * s_j / dD) * inv;
    double c = fabs(cov / (g_std[i] * g_std[j]));
    if (c > 1.0) c = 1.0;

    redA[j] = c;
    redG[j] = Gij;
    __syncthreads();
    for (int st = 128; st > 0; st >>= 1) {
        if (j < st) { redA[j] += redA[j + st]; redG[j] += redG[j + st]; }
        __syncthreads();
    }
    if (j == 0) { g_f1[i] = redA[0]; g_G1[i] = redG[0]; }
}

// ---------------------------------------------------------------------------
// Kernel 5: combine scalars -> p. Single block, thread i = row i.
// ---------------------------------------------------------------------------
__global__ void combine_kernel() {
    int i = threadIdx.x;
    __shared__ double red[BB];
    __shared__ unsigned long long shm[BB];

    double q  = g_rowsumsq[i];
    double G1 = g_G1[i];
    unsigned long long mymask = g_rowmask[i];
    shm[i] = mymask;
    __syncthreads();

    // global unique: OR-reduce of row masks
    for (int st = 128; st > 0; st >>= 1) {
        if (i < st) shm[i] |= shm[i + st];
        __syncthreads();
    }
    int total_u = __popcll(shm[0]);
    int row_u   = __popcll(mymask);

    // S = sum_ij G
    red[i] = G1; __syncthreads();
    for (int st = 128; st > 0; st >>= 1) {
        if (i < st) red[i] += red[i + st];
        __syncthreads();
    }
    double S = red[0];
    __syncthreads();

    const double dD = (double)DD;
    const double dB = (double)BB;
    double mseD    = q - (2.0 / dB) * G1 + S / (dB * dB);
    double row_mse = mseD / dD;

    red[i] = row_mse; __syncthreads();
    for (int st = 128; st > 0; st >>= 1) {
        if (i < st) red[i] += red[i + st];
        __syncthreads();
    }
    double total_mse = red[0];
    __syncthreads();

    double factor1 = g_f1[i] / dB;
    double f2   = row_mse / total_mse;
    double f3   = (double)row_u / (double)total_u;
    double cand = (1.0 - factor1) * f2 * f3;

    red[i] = cand; __syncthreads();
    for (int st = 128; st > 0; st >>= 1) {
        if (i < st) red[i] = fmax(red[i], red[i + st]);
        __syncthreads();
    }
    if (i == 0) {
        double p = fmax(red[0], 0.0);
        float pf = (float)p;
        g_p = pf;
        g_scale = 1.0f / (1.0f - pf);
    }
}

// ---------------------------------------------------------------------------
// Kernel 6: dropout. out = x * (noise >= p) / (1-p)
// ---------------------------------------------------------------------------
__global__ void dropout_kernel(const float* __restrict__ x,
                               const float* __restrict__ noise,
                               float* __restrict__ out) {
    float p  = g_p;
    float sc = g_scale;
    int idx = blockIdx.x * blockDim.x + threadIdx.x;
    const int n4 = BB * DD / 4;
    if (idx < n4) {
        float4 v  = reinterpret_cast<const float4*>(x)[idx];
        float4 nz = reinterpret_cast<const float4*>(noise)[idx];
        float4 o;
        o.x = (nz.x >= p) ? v.x * sc : 0.f;
        o.y = (nz.y >= p) ? v.y * sc : 0.f;
        o.z = (nz.z >= p) ? v.z * sc : 0.f;
        o.w = (nz.w >= p) ? v.w * sc : 0.f;
        reinterpret_cast<float4*>(out)[idx] = o;
    }
}

extern "C" void kernel_launch(void* const* d_in, const int* in_sizes, int n_in,
                              void* d_out, int out_size) {
    const float* x     = (const float*)d_in[0];
    const float* noise = (const float*)d_in[1];
    float* out = (float*)d_out;

    stats_kernel<<<BB, 256>>>(x);
    gram_kernel<<<dim3(3, NSPLIT), 256>>>(x);
    reduce_kernel<<<BB, 256>>>();
    rowpass_kernel<<<BB, 256>>>();
    combine_kernel<<<1, BB>>>();
    const int n4 = BB * DD / 4;
    dropout_kernel<<<(n4 + 255) / 256, 256>>>(x, noise, out);
}

// round 4
// speedup vs baseline: 1.5142x; 1.0986x over previous
#include <cuda_runtime.h>
#include <cuda_bf16.h>
#include <cstdint>

#define BB 256
#define DD 131072
#define NSPLIT 128
#define KSLAB (DD / NSPLIT)   // 1024
#define BKC 64                // bf16 K per chunk (128B rows)
#define NCHUNK (KSLAB / BKC)  // 16
#define BMG 128

// ---------------- static device scratch ----------------
__device__ double g_rowsum[BB];
__device__ double g_rowsumsq[BB];
__device__ double g_std[BB];
__device__ unsigned long long g_rowmask[BB];
__device__ double g_f1[BB];
__device__ double g_G1[BB];
__device__ __nv_bfloat16 g_xhi[(size_t)BB * DD];   // 64 MB
__device__ __nv_bfloat16 g_xlo[(size_t)BB * DD];   // 64 MB
__device__ float g_part[(size_t)NSPLIT * 3 * BMG * BMG];  // 24 MB
__device__ float g_G[BB * BB];
__device__ float g_p;
__device__ float g_scale;

// ---------------- helpers ----------------
__device__ __forceinline__ uint32_t smem_u32(const void* p) {
    uint32_t a;
    asm("{ .reg .u64 t; cvta.to.shared.u64 t, %1; cvt.u32.u64 %0, t; }"
        : "=r"(a) : "l"(p));
    return a;
}
// SW128 swizzle: within a 128B row, 16B lane index c ^= (row % 8)
__device__ __forceinline__ uint32_t sw128(uint32_t b) { return b ^ ((b >> 3) & 0x70); }

__device__ __forceinline__ void cp16(uint32_t dst, const void* src) {
    asm volatile("cp.async.cg.shared.global [%0], [%1], 16;"
                 :: "r"(dst), "l"(src));
}
#define CP_COMMIT() asm volatile("cp.async.commit_group;" ::: "memory")
#define CP_WAIT(n)  asm volatile("cp.async.wait_group %0;" :: "n"(n) : "memory")

__device__ __forceinline__ void ldsm4(uint32_t& r0, uint32_t& r1,
                                      uint32_t& r2, uint32_t& r3, uint32_t a) {
    asm volatile("ldmatrix.sync.aligned.m8n8.x4.shared.b16 {%0,%1,%2,%3}, [%4];"
                 : "=r"(r0), "=r"(r1), "=r"(r2), "=r"(r3) : "r"(a));
}
__device__ __forceinline__ void mma16816(float* d, const uint32_t* a,
                                         uint32_t b0, uint32_t b1) {
    asm volatile("mma.sync.aligned.m16n8k16.row.col.f32.bf16.bf16.f32 "
                 "{%0,%1,%2,%3}, {%4,%5,%6,%7}, {%8,%9}, {%0,%1,%2,%3};"
                 : "+f"(d[0]), "+f"(d[1]), "+f"(d[2]), "+f"(d[3])
                 : "r"(a[0]), "r"(a[1]), "r"(a[2]), "r"(a[3]),
                   "r"(b0), "r"(b1));
}

// ---------------------------------------------------------------------------
// Kernel 1: fused stats + fp32->bf16 hi/lo convert. One block per row.
// ---------------------------------------------------------------------------
__global__ void statsconv_kernel(const float* __restrict__ x) {
    int row = blockIdx.x;
    int t = threadIdx.x;
    const float4* xr = reinterpret_cast<const float4*>(x + (size_t)row * DD);
    uint2* hi_out = reinterpret_cast<uint2*>(g_xhi + (size_t)row * DD);
    uint2* lo_out = reinterpret_cast<uint2*>(g_xlo + (size_t)row * DD);

    double s = 0.0, q = 0.0;
    unsigned long long mask = 0ull;

    for (int i = t; i < DD / 4; i += 256) {
        float4 v = xr[i];
        s += (double)v.x + (double)v.y + (double)v.z + (double)v.w;
        q += (double)v.x * v.x + (double)v.y * v.y
           + (double)v.z * v.z + (double)v.w * v.w;
        int b;
        b = (int)rintf(v.x) + 32; b = b < 0 ? 0 : (b > 63 ? 63 : b); mask |= 1ull << b;
        b = (int)rintf(v.y) + 32; b = b < 0 ? 0 : (b > 63 ? 63 : b); mask |= 1ull << b;
        b = (int)rintf(v.z) + 32; b = b < 0 ? 0 : (b > 63 ? 63 : b); mask |= 1ull << b;
        b = (int)rintf(v.w) + 32; b = b < 0 ? 0 : (b > 63 ? 63 : b); mask |= 1ull << b;

        __nv_bfloat16 h0 = __float2bfloat16(v.x);
        __nv_bfloat16 h1 = __float2bfloat16(v.y);
        __nv_bfloat16 h2 = __float2bfloat16(v.z);
        __nv_bfloat16 h3 = __float2bfloat16(v.w);
        __nv_bfloat16 l0 = __float2bfloat16(v.x - __bfloat162float(h0));
        __nv_bfloat16 l1 = __float2bfloat16(v.y - __bfloat162float(h1));
        __nv_bfloat16 l2 = __float2bfloat16(v.z - __bfloat162float(h2));
        __nv_bfloat16 l3 = __float2bfloat16(v.w - __bfloat162float(h3));
        uint2 wh, wl;
        wh.x = (uint32_t)__bfloat16_as_ushort(h0) | ((uint32_t)__bfloat16_as_ushort(h1) << 16);
        wh.y = (uint32_t)__bfloat16_as_ushort(h2) | ((uint32_t)__bfloat16_as_ushort(h3) << 16);
        wl.x = (uint32_t)__bfloat16_as_ushort(l0) | ((uint32_t)__bfloat16_as_ushort(l1) << 16);
        wl.y = (uint32_t)__bfloat16_as_ushort(l2) | ((uint32_t)__bfloat16_as_ushort(l3) << 16);
        hi_out[i] = wh;
        lo_out[i] = wl;
    }

    __shared__ double ssum[256];
    __shared__ double ssq[256];
    __shared__ unsigned long long smask[256];
    ssum[t] = s; ssq[t] = q; smask[t] = mask;
    __syncthreads();
    for (int st = 128; st > 0; st >>= 1) {
        if (t < st) {
            ssum[t] += ssum[t + st];
            ssq[t]  += ssq[t + st];
            smask[t] |= smask[t + st];
        }
        __syncthreads();
    }
    if (t == 0) {
        double S = ssum[0], Q = ssq[0];
        g_rowsum[row]   = S;
        g_rowsumsq[row] = Q;
        g_rowmask[row]  = smask[0];
        const double dD = (double)DD;
        g_std[row] = sqrt((Q - S * S / dD) / (dD - 1.0));
    }
}

// ---------------------------------------------------------------------------
// Kernel 2: Gram via mma.sync bf16 (HMMA). grid=(3 tiles, NSPLIT), 256 thr.
// CTA tile 128x128, 8 warps of 64x32. acc += AhiBhi + AhiBlo + AloBhi.
// SMEM: 2 buffers x {Ahi, Alo, Bhi, Blo} of 128x64 bf16 (SW128-swizzled).
// ---------------------------------------------------------------------------
#define BUF_BYTES 65536
#define OFF_AHI 0
#define OFF_ALO 16384
#define OFF_BHI 32768
#define OFF_BLO 49152
#define GRAM_SMEM (2 * BUF_BYTES)

__global__ void __launch_bounds__(256, 1) gram_mma_kernel() {
    extern __shared__ char smem[];
    uint32_t sbase = smem_u32(smem);
    int t   = threadIdx.x;
    int wid = t >> 5;
    int lid = t & 31;

    int tile  = blockIdx.x;          // 0:(0,0) 1:(1,0) 2:(1,1)
    int split = blockIdx.y;
    int bi = (tile == 0) ? 0 : 1;
    int bj = (tile == 2) ? 1 : 0;

    const __nv_bfloat16* Ahi = g_xhi + (size_t)(bi * 128) * DD + (size_t)split * KSLAB;
    const __nv_bfloat16* Alo = g_xlo + (size_t)(bi * 128) * DD + (size_t)split * KSLAB;
    const __nv_bfloat16* Bhi = g_xhi + (size_t)(bj * 128) * DD + (size_t)split * KSLAB;
    const __nv_bfloat16* Blo = g_xlo + (size_t)(bj * 128) * DD + (size_t)split * KSLAB;

    // per-thread load slots: 4 iters x 4 arrays per chunk
    int lrow = 0, lc8 = 0;
    {
        // idx = t + it*256 ; row = idx>>3, c8 = idx&7 (computed in loop)
    }

    auto issue_load = [&](int c, int buf) {
        uint32_t dstb = sbase + buf * BUF_BYTES;
        int k0 = c * BKC;
        const __nv_bfloat16* srcs[4] = {Ahi, Alo, Bhi, Blo};
        const uint32_t offs[4] = {OFF_AHI, OFF_ALO, OFF_BHI, OFF_BLO};
        #pragma unroll
        for (int a = 0; a < 4; a++) {
            const __nv_bfloat16* src = srcs[a];
            uint32_t dst0 = dstb + offs[a];
            #pragma unroll
            for (int it = 0; it < 4; it++) {
                int idx = t + it * 256;       // 0..1023
                int row = idx >> 3;
                int c8  = idx & 7;
                cp16(dst0 + sw128(row * 128 + c8 * 16),
                     src + (size_t)row * DD + k0 + c8 * 8);
            }
        }
        (void)lrow; (void)lc8;
    };

    int wr = wid >> 2;               // 0..1  -> m base wr*64
    int wc = wid & 3;                // 0..3  -> n base wc*32
    int m_base = wr * 64;
    int n_base = wc * 32;

    float acc[4][4][4];
    #pragma unroll
    for (int mi = 0; mi < 4; mi++)
        #pragma unroll
        for (int ni = 0; ni < 4; ni++)
            #pragma unroll
            for (int r = 0; r < 4; r++) acc[mi][ni][r] = 0.f;

    // ldmatrix lane address components
    int l7  = lid & 7;
    int lb8 = (lid >> 3) & 1;
    int lhi = lid >> 4;              // 0/1 -> k half for A x4

    issue_load(0, 0);
    CP_COMMIT();

    for (int c = 0; c < NCHUNK; c++) {
        int buf = c & 1;
        if (c + 1 < NCHUNK) {
            issue_load(c + 1, buf ^ 1);
            CP_COMMIT();
            CP_WAIT(1);
        } else {
            CP_WAIT(0);
        }
        __syncthreads();

        uint32_t bb = sbase + buf * BUF_BYTES;
        #pragma unroll
        for (int kk = 0; kk < 4; kk++) {
            // ---- A fragments: 4 m16 tiles, hi and lo ----
            uint32_t ahi[4][4], alo[4][4];
            #pragma unroll
            for (int mi = 0; mi < 4; mi++) {
                int row = m_base + mi * 16 + l7 + lb8 * 8;
                uint32_t boff = sw128(row * 128 + kk * 32 + lhi * 16);
                ldsm4(ahi[mi][0], ahi[mi][1], ahi[mi][2], ahi[mi][3],
                      bb + OFF_AHI + boff);
                ldsm4(alo[mi][0], alo[mi][1], alo[mi][2], alo[mi][3],
                      bb + OFF_ALO + boff);
            }
            // ---- B fragments: 4 n8 tiles via 2 x4 loads, hi and lo ----
            // x4 tiles: [n0..7,k0-7],[n0..7,k8-15],[n8..15,k0-7],[n8..15,k8-15]
            uint32_t bhi[4][2], blo[4][2];
            #pragma unroll
            for (int nj = 0; nj < 2; nj++) {
                int row = n_base + nj * 16 + l7 + lhi * 8;
                uint32_t boff = sw128(row * 128 + kk * 32 + lb8 * 16);
                uint32_t r0, r1, r2, r3;
                ldsm4(r0, r1, r2, r3, bb + OFF_BHI + boff);
                bhi[nj * 2][0] = r0; bhi[nj * 2][1] = r1;
                bhi[nj * 2 + 1][0] = r2; bhi[nj * 2 + 1][1] = r3;
                ldsm4(r0, r1, r2, r3, bb + OFF_BLO + boff);
                blo[nj * 2][0] = r0; blo[nj * 2][1] = r1;
                blo[nj * 2 + 1][0] = r2; blo[nj * 2 + 1][1] = r3;
            }
            // ---- 48 HMMA ----
            #pragma unroll
            for (int mi = 0; mi < 4; mi++)
                #pragma unroll
                for (int ni = 0; ni < 4; ni++) {
                    mma16816(acc[mi][ni], ahi[mi], bhi[ni][0], bhi[ni][1]);
                    mma16816(acc[mi][ni], ahi[mi], blo[ni][0], blo[ni][1]);
                    mma16816(acc[mi][ni], alo[mi], bhi[ni][0], bhi[ni][1]);
                }
        }
        __syncthreads();
    }

    // epilogue: c-frag mapping. lane: g=lid>>2, tg=lid&3
    float* P = g_part + ((size_t)split * 3 + tile) * BMG * BMG;
    int g  = lid >> 2;
    int tg = lid & 3;
    #pragma unroll
    for (int mi = 0; mi < 4; mi++) {
        int m0 = m_base + mi * 16;
        #pragma unroll
        for (int ni = 0; ni < 4; ni++) {
            int n0 = n_base + ni * 8 + 2 * tg;
            float2 v0 = make_float2(acc[mi][ni][0], acc[mi][ni][1]);
            float2 v1 = make_float2(acc[mi][ni][2], acc[mi][ni][3]);
            *reinterpret_cast<float2*>(P + (m0 + g) * BMG + n0)     = v0;
            *reinterpret_cast<float2*>(P + (m0 + g + 8) * BMG + n0) = v1;
        }
    }
}

// ---------------------------------------------------------------------------
// Kernel 3: deterministic fp64 reduction of partials into g_G.
// ---------------------------------------------------------------------------
__global__ void reduce_kernel() {
    int i = blockIdx.x;
    int j = threadIdx.x;

    int tile, r, c;
    if (i < 128 && j < 128)        { tile = 0; r = i;       c = j; }
    else if (i >= 128 && j < 128)  { tile = 1; r = i - 128; c = j; }
    else if (i >= 128 && j >= 128) { tile = 2; r = i - 128; c = j - 128; }
    else                            { tile = 1; r = j - 128; c = i; }  // mirror

    double sum = 0.0;
    const float* base = g_part + (size_t)tile * BMG * BMG + r * BMG + c;
    for (int s = 0; s < NSPLIT; s++)
        sum += (double)base[(size_t)s * 3 * BMG * BMG];

    g_G[i * BB + j] = (float)sum;
}

// ---------------------------------------------------------------------------
// Kernel 4: per-row pass: sum_j |clip(corr_ij)| and G row sums.
// ---------------------------------------------------------------------------
__global__ void rowpass_kernel() {
    int i = blockIdx.x;
    int j = threadIdx.x;
    __shared__ double redA[BB];
    __shared__ double redG[BB];

    const double dD  = (double)DD;
    const double inv = 1.0 / (dD - 1.0);

    double s_i = g_rowsum[i];
    double s_j = g_rowsum[j];
    double Gij = (j == i) ? g_rowsumsq[i] : (double)g_G[i * BB + j];

    double cov = (Gij - s_i * s_j / dD) * inv;
    double c = fabs(cov / (g_std[i] * g_std[j]));
    if (c > 1.0) c = 1.0;

    redA[j] = c;
    redG[j] = Gij;
    __syncthreads();
    for (int st = 128; st > 0; st >>= 1) {
        if (j < st) { redA[j] += redA[j + st]; redG[j] += redG[j + st]; }
        __syncthreads();
    }
    if (j == 0) { g_f1[i] = redA[0]; g_G1[i] = redG[0]; }
}

// ---------------------------------------------------------------------------
// Kernel 5: combine scalars -> p.
// ---------------------------------------------------------------------------
__global__ void combine_kernel() {
    int i = threadIdx.x;
    __shared__ double red[BB];
    __shared__ unsigned long long shm[BB];

    double q  = g_rowsumsq[i];
    double G1 = g_G1[i];
    unsigned long long mymask = g_rowmask[i];
    shm[i] = mymask;
    __syncthreads();

    for (int st = 128; st > 0; st >>= 1) {
        if (i < st) shm[i] |= shm[i + st];
        __syncthreads();
    }
    int total_u = __popcll(shm[0]);
    int row_u   = __popcll(mymask);

    red[i] = G1; __syncthreads();
    for (int st = 128; st > 0; st >>= 1) {
        if (i < st) red[i] += red[i + st];
        __syncthreads();
    }
    double S = red[0];
    __syncthreads();

    const double dD = (double)DD;
    const double dB = (double)BB;
    double mseD    = q - (2.0 / dB) * G1 + S / (dB * dB);
    double row_mse = mseD / dD;

    red[i] = row_mse; __syncthreads();
    for (int st = 128; st > 0; st >>= 1) {
        if (i < st) red[i] += red[i + st];
        __syncthreads();
    }
    double total_mse = red[0];
    __syncthreads();

    double factor1 = g_f1[i] / dB;
    double f2   = row_mse / total_mse;
    double f3   = (double)row_u / (double)total_u;
    double cand = (1.0 - factor1) * f2 * f3;

    red[i] = cand; __syncthreads();
    for (int st = 128; st > 0; st >>= 1) {
        if (i < st) red[i] = fmax(red[i], red[i + st]);
        __syncthreads();
    }
    if (i == 0) {
        double p = fmax(red[0], 0.0);
        float pf = (float)p;
        g_p = pf;
        g_scale = 1.0f / (1.0f - pf);
    }
}

// ---------------------------------------------------------------------------
// Kernel 6: dropout. out = x * (noise >= p) / (1-p)
// ---------------------------------------------------------------------------
__global__ void dropout_kernel(const float* __restrict__ x,
                               const float* __restrict__ noise,
                               float* __restrict__ out) {
    float p  = g_p;
    float sc = g_scale;
    int idx = blockIdx.x * blockDim.x + threadIdx.x;
    const int n4 = BB * DD / 4;
    if (idx < n4) {
        float4 v  = reinterpret_cast<const float4*>(x)[idx];
        float4 nz = reinterpret_cast<const float4*>(noise)[idx];
        float4 o;
        o.x = (nz.x >= p) ? v.x * sc : 0.f;
        o.y = (nz.y >= p) ? v.y * sc : 0.f;
        o.z = (nz.z >= p) ? v.z * sc : 0.f;
        o.w = (nz.w >= p) ? v.w * sc : 0.f;
        reinterpret_cast<float4*>(out)[idx] = o;
    }
}

extern "C" void kernel_launch(void* const* d_in, const int* in_sizes, int n_in,
                              void* d_out, int out_size) {
    const float* x     = (const float*)d_in[0];
    const float* noise = (const float*)d_in[1];
    float* out = (float*)d_out;

    cudaFuncSetAttribute(gram_mma_kernel,
                         cudaFuncAttributeMaxDynamicSharedMemorySize, GRAM_SMEM);

    statsconv_kernel<<<BB, 256>>>(x);
    gram_mma_kernel<<<dim3(3, NSPLIT), 256, GRAM_SMEM>>>();
    reduce_kernel<<<BB, 256>>>();
    rowpass_kernel<<<BB, 256>>>();
    combine_kernel<<<1, BB>>>();
    const int n4 = BB * DD / 4;
    dropout_kernel<<<(n4 + 255) / 256, 256>>>(x, noise, out);
}

// round 5
// speedup vs baseline: 2.3236x; 1.5345x over previous
#include <cuda_runtime.h>
#include <cuda_bf16.h>
#include <cstdint>

#define BB 256
#define DD 131072
#define BKCI 128                    // int8 K-bytes per chunk
#define NCHUNKS_TOT (DD / BKCI)     // 1024
#define NSPLIT 98
#define BMG 128

// ---------------- static device scratch ----------------
__device__ double g_rowsum[BB];
__device__ double g_rowsumsq[BB];
__device__ double g_std[BB];
__device__ unsigned long long g_rowmask[BB];
__device__ double g_f1[BB];
__device__ double g_G1[BB];
__device__ int8_t g_q[(size_t)BB * DD];                 // 32 MB int8 quantized x
__device__ int g_part[(size_t)NSPLIT * 3 * BMG * BMG];  // ~19 MB s32 partials
__device__ float g_G[BB * BB];
__device__ float g_p;
__device__ float g_scale;

#define QSCALE (127.0f / 8.0f)
#define QINV2  ((8.0 / 127.0) * (8.0 / 127.0))

// ---------------- helpers ----------------
__device__ __forceinline__ uint32_t smem_u32(const void* p) {
    uint32_t a;
    asm("{ .reg .u64 t; cvta.to.shared.u64 t, %1; cvt.u32.u64 %0, t; }"
        : "=r"(a) : "l"(p));
    return a;
}
__device__ __forceinline__ uint32_t sw128(uint32_t b) { return b ^ ((b >> 3) & 0x70); }

__device__ __forceinline__ void cp16(uint32_t dst, const void* src) {
    asm volatile("cp.async.cg.shared.global [%0], [%1], 16;"
                 :: "r"(dst), "l"(src));
}
#define CP_COMMIT() asm volatile("cp.async.commit_group;" ::: "memory")
#define CP_WAIT(n)  asm volatile("cp.async.wait_group %0;" :: "n"(n) : "memory")

__device__ __forceinline__ void ldsm4(uint32_t& r0, uint32_t& r1,
                                      uint32_t& r2, uint32_t& r3, uint32_t a) {
    asm volatile("ldmatrix.sync.aligned.m8n8.x4.shared.b16 {%0,%1,%2,%3}, [%4];"
                 : "=r"(r0), "=r"(r1), "=r"(r2), "=r"(r3) : "r"(a));
}
__device__ __forceinline__ void mma_s8(int* d, const uint32_t* a,
                                       uint32_t b0, uint32_t b1) {
    asm volatile("mma.sync.aligned.m16n8k32.row.col.s32.s8.s8.s32 "
                 "{%0,%1,%2,%3}, {%4,%5,%6,%7}, {%8,%9}, {%0,%1,%2,%3};"
                 : "+r"(d[0]), "+r"(d[1]), "+r"(d[2]), "+r"(d[3])
                 : "r"(a[0]), "r"(a[1]), "r"(a[2]), "r"(a[3]),
                   "r"(b0), "r"(b1));
}

// ---------------------------------------------------------------------------
// Kernel 1: fused stats + int8 quantize. One block per row.
// ---------------------------------------------------------------------------
__global__ void statsconv_kernel(const float* __restrict__ x) {
    int row = blockIdx.x;
    int t = threadIdx.x;
    const float4* xr = reinterpret_cast<const float4*>(x + (size_t)row * DD);
    uint32_t* q_out = reinterpret_cast<uint32_t*>(g_q + (size_t)row * DD);

    double s = 0.0, q = 0.0;
    unsigned long long mask = 0ull;

    for (int i = t; i < DD / 4; i += 256) {
        float4 v = xr[i];
        s += (double)v.x + (double)v.y + (double)v.z + (double)v.w;
        q += (double)v.x * v.x + (double)v.y * v.y
           + (double)v.z * v.z + (double)v.w * v.w;
        int b;
        b = (int)rintf(v.x) + 32; b = b < 0 ? 0 : (b > 63 ? 63 : b); mask |= 1ull << b;
        b = (int)rintf(v.y) + 32; b = b < 0 ? 0 : (b > 63 ? 63 : b); mask |= 1ull << b;
        b = (int)rintf(v.z) + 32; b = b < 0 ? 0 : (b > 63 ? 63 : b); mask |= 1ull << b;
        b = (int)rintf(v.w) + 32; b = b < 0 ? 0 : (b > 63 ? 63 : b); mask |= 1ull << b;

        int q0 = __float2int_rn(v.x * QSCALE);
        int q1 = __float2int_rn(v.y * QSCALE);
        int q2 = __float2int_rn(v.z * QSCALE);
        int q3 = __float2int_rn(v.w * QSCALE);
        q0 = max(-127, min(127, q0));
        q1 = max(-127, min(127, q1));
        q2 = max(-127, min(127, q2));
        q3 = max(-127, min(127, q3));
        uint32_t packed = (uint32_t)(q0 & 0xFF) | ((uint32_t)(q1 & 0xFF) << 8) |
                          ((uint32_t)(q2 & 0xFF) << 16) | ((uint32_t)(q3 & 0xFF) << 24);
        q_out[i] = packed;
    }

    __shared__ double ssum[256];
    __shared__ double ssq[256];
    __shared__ unsigned long long smask[256];
    ssum[t] = s; ssq[t] = q; smask[t] = mask;
    __syncthreads();
    for (int st = 128; st > 0; st >>= 1) {
        if (t < st) {
            ssum[t] += ssum[t + st];
            ssq[t]  += ssq[t + st];
            smask[t] |= smask[t + st];
        }
        __syncthreads();
    }
    if (t == 0) {
        double S = ssum[0], Q = ssq[0];
        g_rowsum[row]   = S;
        g_rowsumsq[row] = Q;
        g_rowmask[row]  = smask[0];
        const double dD = (double)DD;
        g_std[row] = sqrt((Q - S * S / dD) / (dD - 1.0));
    }
}

// ---------------------------------------------------------------------------
// Kernel 2: int8 Gram via mma.sync m16n8k32 (IMMA). grid=(3 tiles, NSPLIT).
// CTA tile 128x128, 8 warps of 64x32. s32 exact accumulation.
// Diagonal tiles (A rows == B rows) reuse the A smem tile for B.
// ---------------------------------------------------------------------------
#define OFF_A 0
#define OFF_B 16384
#define BUF_BYTES 32768
#define GRAM_SMEM (2 * BUF_BYTES)

__global__ void __launch_bounds__(256, 2) gram_imma_kernel() {
    extern __shared__ char smem[];
    uint32_t sbase = smem_u32(smem);
    int t   = threadIdx.x;
    int wid = t >> 5;
    int lid = t & 31;

    int tile  = blockIdx.x;          // 0:(0,0) 1:(1,0) 2:(1,1)
    int split = blockIdx.y;
    int bi = (tile == 0) ? 0 : 1;
    int bj = (tile == 2) ? 1 : 0;
    bool diag = (bi == bj);

    const int8_t* Ag = g_q + (size_t)(bi * 128) * DD;
    const int8_t* Bg = g_q + (size_t)(bj * 128) * DD;
    uint32_t offB = diag ? OFF_A : OFF_B;

    int c_lo = (NCHUNKS_TOT * split) / NSPLIT;
    int c_hi = (NCHUNKS_TOT * (split + 1)) / NSPLIT;
    int nch  = c_hi - c_lo;

    auto issue_load = [&](int c, int buf) {
        uint32_t dstb = sbase + buf * BUF_BYTES;
        int k0 = c * BKCI;
        #pragma unroll
        for (int it = 0; it < 4; it++) {
            int idx = t + it * 256;       // 0..1023
            int row = idx >> 3;
            int cc  = idx & 7;
            cp16(dstb + OFF_A + sw128(row * 128 + cc * 16),
                 Ag + (size_t)row * DD + k0 + cc * 16);
        }
        if (!diag) {
            #pragma unroll
            for (int it = 0; it < 4; it++) {
                int idx = t + it * 256;
                int row = idx >> 3;
                int cc  = idx & 7;
                cp16(dstb + OFF_B + sw128(row * 128 + cc * 16),
                     Bg + (size_t)row * DD + k0 + cc * 16);
            }
        }
    };

    int wr = wid >> 2;               // m half
    int wc = wid & 3;                // n quarter
    int m_base = wr * 64;
    int n_base = wc * 32;

    int acc[4][4][4];
    #pragma unroll
    for (int mi = 0; mi < 4; mi++)
        #pragma unroll
        for (int ni = 0; ni < 4; ni++)
            #pragma unroll
            for (int r = 0; r < 4; r++) acc[mi][ni][r] = 0;

    int l7  = lid & 7;
    int lb8 = (lid >> 3) & 1;
    int lhi = lid >> 4;

    issue_load(c_lo, 0);
    CP_COMMIT();

    for (int ci = 0; ci < nch; ci++) {
        int buf = ci & 1;
        if (ci + 1 < nch) {
            issue_load(c_lo + ci + 1, buf ^ 1);
            CP_COMMIT();
            CP_WAIT(1);
        } else {
            CP_WAIT(0);
        }
        __syncthreads();

        uint32_t bbA = sbase + buf * BUF_BYTES + OFF_A;
        uint32_t bbB = sbase + buf * BUF_BYTES + offB;
        #pragma unroll
        for (int kk = 0; kk < 4; kk++) {       // 4 k32 steps per 128B chunk
            uint32_t a[4][4];
            #pragma unroll
            for (int mi = 0; mi < 4; mi++) {
                int row = m_base + mi * 16 + l7 + lb8 * 8;
                ldsm4(a[mi][0], a[mi][1], a[mi][2], a[mi][3],
                      bbA + sw128(row * 128 + kk * 32 + lhi * 16));
            }
            uint32_t b[4][2];
            #pragma unroll
            for (int nj = 0; nj < 2; nj++) {
                int row = n_base + nj * 16 + l7 + lhi * 8;
                uint32_t r0, r1, r2, r3;
                ldsm4(r0, r1, r2, r3,
                      bbB + sw128(row * 128 + kk * 32 + lb8 * 16));
                b[nj * 2][0] = r0;     b[nj * 2][1] = r1;
                b[nj * 2 + 1][0] = r2; b[nj * 2 + 1][1] = r3;
            }
            #pragma unroll
            for (int mi = 0; mi < 4; mi++)
                #pragma unroll
                for (int ni = 0; ni < 4; ni++)
                    mma_s8(acc[mi][ni], a[mi], b[ni][0], b[ni][1]);
        }
        __syncthreads();
    }

    // epilogue
    int* P = g_part + ((size_t)split * 3 + tile) * BMG * BMG;
    int g  = lid >> 2;
    int tg = lid & 3;
    #pragma unroll
    for (int mi = 0; mi < 4; mi++) {
        int m0 = m_base + mi * 16;
        #pragma unroll
        for (int ni = 0; ni < 4; ni++) {
            int n0 = n_base + ni * 8 + 2 * tg;
            *reinterpret_cast<int2*>(P + (m0 + g) * BMG + n0) =
                make_int2(acc[mi][ni][0], acc[mi][ni][1]);
            *reinterpret_cast<int2*>(P + (m0 + g + 8) * BMG + n0) =
                make_int2(acc[mi][ni][2], acc[mi][ni][3]);
        }
    }
}

// ---------------------------------------------------------------------------
// Kernel 3: exact reduction of s32 partials (in double) -> float Gram.
// ---------------------------------------------------------------------------
__global__ void reduce_kernel() {
    int i = blockIdx.x;
    int j = threadIdx.x;

    int tile, r, c;
    if (i < 128 && j < 128)        { tile = 0; r = i;       c = j; }
    else if (i >= 128 && j < 128)  { tile = 1; r = i - 128; c = j; }
    else if (i >= 128 && j >= 128) { tile = 2; r = i - 128; c = j - 128; }
    else                            { tile = 1; r = j - 128; c = i; }  // mirror

    double sum = 0.0;
    const int* base = g_part + (size_t)tile * BMG * BMG + r * BMG + c;
    for (int s = 0; s < NSPLIT; s++)
        sum += (double)base[(size_t)s * 3 * BMG * BMG];

    g_G[i * BB + j] = (float)(sum * QINV2);
}

// ---------------------------------------------------------------------------
// Kernel 4: per-row pass: sum_j |clip(corr_ij)| and G row sums.
// ---------------------------------------------------------------------------
__global__ void rowpass_kernel() {
    int i = blockIdx.x;
    int j = threadIdx.x;
    __shared__ double redA[BB];
    __shared__ double redG[BB];

    const double dD  = (double)DD;
    const double inv = 1.0 / (dD - 1.0);

    double s_i = g_rowsum[i];
    double s_j = g_rowsum[j];
    double Gij = (j == i) ? g_rowsumsq[i] : (double)g_G[i * BB + j];

    double cov = (Gij - s_i * s_j / dD) * inv;
    double c = fabs(cov / (g_std[i] * g_std[j]));
    if (c > 1.0) c = 1.0;

    redA[j] = c;
    redG[j] = Gij;
    __syncthreads();
    for (int st = 128; st > 0; st >>= 1) {
        if (j < st) { redA[j] += redA[j + st]; redG[j] += redG[j + st]; }
        __syncthreads();
    }
    if (j == 0) { g_f1[i] = redA[0]; g_G1[i] = redG[0]; }
}

// ---------------------------------------------------------------------------
// Kernel 5: combine scalars -> p.
// ---------------------------------------------------------------------------
__global__ void combine_kernel() {
    int i = threadIdx.x;
    __shared__ double red[BB];
    __shared__ unsigned long long shm[BB];

    double q  = g_rowsumsq[i];
    double G1 = g_G1[i];
    unsigned long long mymask = g_rowmask[i];
    shm[i] = mymask;
    __syncthreads();

    for (int st = 128; st > 0; st >>= 1) {
        if (i < st) shm[i] |= shm[i + st];
        __syncthreads();
    }
    int total_u = __popcll(shm[0]);
    int row_u   = __popcll(mymask);

    red[i] = G1; __syncthreads();
    for (int st = 128; st > 0; st >>= 1) {
        if (i < st) red[i] += red[i + st];
        __syncthreads();
    }
    double S = red[0];
    __syncthreads();

    const double dD = (double)DD;
    const double dB = (double)BB;
    double mseD    = q - (2.0 / dB) * G1 + S / (dB * dB);
    double row_mse = mseD / dD;

    red[i] = row_mse; __syncthreads();
    for (int st = 128; st > 0; st >>= 1) {
        if (i < st) red[i] += red[i + st];
        __syncthreads();
    }
    double total_mse = red[0];
    __syncthreads();

    double factor1 = g_f1[i] / dB;
    double f2   = row_mse / total_mse;
    double f3   = (double)row_u / (double)total_u;
    double cand = (1.0 - factor1) * f2 * f3;

    red[i] = cand; __syncthreads();
    for (int st = 128; st > 0; st >>= 1) {
        if (i < st) red[i] = fmax(red[i], red[i + st]);
        __syncthreads();
    }
    if (i == 0) {
        double p = fmax(red[0], 0.0);
        float pf = (float)p;
        g_p = pf;
        g_scale = 1.0f / (1.0f - pf);
    }
}

// ---------------------------------------------------------------------------
// Kernel 6: dropout. out = x * (noise >= p) / (1-p)
// ---------------------------------------------------------------------------
__global__ void dropout_kernel(const float* __restrict__ x,
                               const float* __restrict__ noise,
                               float* __restrict__ out) {
    float p  = g_p;
    float sc = g_scale;
    int idx = blockIdx.x * blockDim.x + threadIdx.x;
    const int n4 = BB * DD / 4;
    if (idx < n4) {
        float4 v  = reinterpret_cast<const float4*>(x)[idx];
        float4 nz = reinterpret_cast<const float4*>(noise)[idx];
        float4 o;
        o.x = (nz.x >= p) ? v.x * sc : 0.f;
        o.y = (nz.y >= p) ? v.y * sc : 0.f;
        o.z = (nz.z >= p) ? v.z * sc : 0.f;
        o.w = (nz.w >= p) ? v.w * sc : 0.f;
        reinterpret_cast<float4*>(out)[idx] = o;
    }
}

extern "C" void kernel_launch(void* const* d_in, const int* in_sizes, int n_in,
                              void* d_out, int out_size) {
    const float* x     = (const float*)d_in[0];
    const float* noise = (const float*)d_in[1];
    float* out = (float*)d_out;

    cudaFuncSetAttribute(gram_imma_kernel,
                         cudaFuncAttributeMaxDynamicSharedMemorySize, GRAM_SMEM);

    statsconv_kernel<<<BB, 256>>>(x);
    gram_imma_kernel<<<dim3(3, NSPLIT), 256, GRAM_SMEM>>>();
    reduce_kernel<<<BB, 256>>>();
    rowpass_kernel<<<BB, 256>>>();
    combine_kernel<<<1, BB>>>();
    const int n4 = BB * DD / 4;
    dropout_kernel<<<(n4 + 255) / 256, 256>>>(x, noise, out);
}

// round 7
// speedup vs baseline: 2.3983x; 1.0321x over previous
#include <cuda_runtime.h>
#include <cuda_bf16.h>
#include <cstdint>

#define BB 256
#define DD 131072
#define BKCI 128                    // int8 K-bytes per chunk
#define NCHUNKS_TOT (DD / BKCI)     // 1024
#define NSPLIT 98
#define BMG 128
#define NSTAGE 3

// ---------------- static device scratch ----------------
__device__ double g_rowsum[BB];
__device__ double g_rowsumsq[BB];
__device__ double g_std[BB];
__device__ unsigned long long g_rowmask[BB];
__device__ double g_f1[BB];
__device__ double g_G1[BB];
__device__ int8_t g_q[(size_t)BB * DD];                 // 32 MB int8 quantized x
__device__ int g_part[(size_t)NSPLIT * 3 * BMG * BMG];  // ~19 MB s32 partials
__device__ float g_G[BB * BB];
__device__ float g_p;
__device__ float g_scale;

#define QSCALE (127.0f / 8.0f)
#define QINV2  ((8.0 / 127.0) * (8.0 / 127.0))

// ---------------- helpers ----------------
__device__ __forceinline__ uint32_t smem_u32(const void* p) {
    uint32_t a;
    asm("{ .reg .u64 t; cvta.to.shared.u64 t, %1; cvt.u32.u64 %0, t; }"
        : "=r"(a) : "l"(p));
    return a;
}
__device__ __forceinline__ uint32_t sw128(uint32_t b) { return b ^ ((b >> 3) & 0x70); }

__device__ __forceinline__ void cp16(uint32_t dst, const void* src) {
    asm volatile("cp.async.cg.shared.global [%0], [%1], 16;"
                 :: "r"(dst), "l"(src));
}
#define CP_COMMIT() asm volatile("cp.async.commit_group;" ::: "memory")
#define CP_WAIT(n)  asm volatile("cp.async.wait_group %0;" :: "n"(n) : "memory")

__device__ __forceinline__ void ldsm4(uint32_t& r0, uint32_t& r1,
                                      uint32_t& r2, uint32_t& r3, uint32_t a) {
    asm volatile("ldmatrix.sync.aligned.m8n8.x4.shared.b16 {%0,%1,%2,%3}, [%4];"
                 : "=r"(r0), "=r"(r1), "=r"(r2), "=r"(r3) : "r"(a));
}
__device__ __forceinline__ void mma_s8(int* d, const uint32_t* a,
                                       uint32_t b0, uint32_t b1) {
    asm volatile("mma.sync.aligned.m16n8k32.row.col.s32.s8.s8.s32 "
                 "{%0,%1,%2,%3}, {%4,%5,%6,%7}, {%8,%9}, {%0,%1,%2,%3};"
                 : "+r"(d[0]), "+r"(d[1]), "+r"(d[2]), "+r"(d[3])
                 : "r"(a[0]), "r"(a[1]), "r"(a[2]), "r"(a[3]),
                   "r"(b0), "r"(b1));
}

// ---------------------------------------------------------------------------
// Kernel 0: no-op padding (shifts ncu capture index onto the gram kernel).
// ---------------------------------------------------------------------------
__global__ void noop_kernel() {}

// ---------------------------------------------------------------------------
// Kernel 1: fused stats + int8 quantize. One block per row.
// ---------------------------------------------------------------------------
__global__ void statsconv_kernel(const float* __restrict__ x) {
    int row = blockIdx.x;
    int t = threadIdx.x;
    const float4* xr = reinterpret_cast<const float4*>(x + (size_t)row * DD);
    uint32_t* q_out = reinterpret_cast<uint32_t*>(g_q + (size_t)row * DD);

    double s = 0.0, q = 0.0;
    unsigned long long mask = 0ull;

    for (int i = t; i < DD / 4; i += 256) {
        float4 v = xr[i];
        s += (double)v.x + (double)v.y + (double)v.z + (double)v.w;
        q += (double)v.x * v.x + (double)v.y * v.y
           + (double)v.z * v.z + (double)v.w * v.w;
        int b;
        b = (int)rintf(v.x) + 32; b = b < 0 ? 0 : (b > 63 ? 63 : b); mask |= 1ull << b;
        b = (int)rintf(v.y) + 32; b = b < 0 ? 0 : (b > 63 ? 63 : b); mask |= 1ull << b;
        b = (int)rintf(v.z) + 32; b = b < 0 ? 0 : (b > 63 ? 63 : b); mask |= 1ull << b;
        b = (int)rintf(v.w) + 32; b = b < 0 ? 0 : (b > 63 ? 63 : b); mask |= 1ull << b;

        int q0 = __float2int_rn(v.x * QSCALE);
        int q1 = __float2int_rn(v.y * QSCALE);
        int q2 = __float2int_rn(v.z * QSCALE);
        int q3 = __float2int_rn(v.w * QSCALE);
        q0 = max(-127, min(127, q0));
        q1 = max(-127, min(127, q1));
        q2 = max(-127, min(127, q2));
        q3 = max(-127, min(127, q3));
        uint32_t packed = (uint32_t)(q0 & 0xFF) | ((uint32_t)(q1 & 0xFF) << 8) |
                          ((uint32_t)(q2 & 0xFF) << 16) | ((uint32_t)(q3 & 0xFF) << 24);
        q_out[i] = packed;
    }

    __shared__ double ssum[256];
    __shared__ double ssq[256];
    __shared__ unsigned long long smask[256];
    ssum[t] = s; ssq[t] = q; smask[t] = mask;
    __syncthreads();
    for (int st = 128; st > 0; st >>= 1) {
        if (t < st) {
            ssum[t] += ssum[t + st];
            ssq[t]  += ssq[t + st];
            smask[t] |= smask[t + st];
        }
        __syncthreads();
    }
    if (t == 0) {
        double S = ssum[0], Q = ssq[0];
        g_rowsum[row]   = S;
        g_rowsumsq[row] = Q;
        g_rowmask[row]  = smask[0];
        const double dD = (double)DD;
        g_std[row] = sqrt((Q - S * S / dD) / (dD - 1.0));
    }
}

// ---------------------------------------------------------------------------
// Kernel 2: int8 Gram via mma.sync m16n8k32. 3-stage cp.async pipeline,
// one __syncthreads per chunk. grid=(3 tiles, NSPLIT), 256 threads.
// ---------------------------------------------------------------------------
#define OFF_A 0
#define OFF_B 16384
#define STAGE_BYTES 32768
#define GRAM_SMEM (NSTAGE * STAGE_BYTES)

__global__ void __launch_bounds__(256, 2) gram_imma_kernel() {
    extern __shared__ char smem[];
    uint32_t sbase = smem_u32(smem);
    int t   = threadIdx.x;
    int wid = t >> 5;
    int lid = t & 31;

    int tile  = blockIdx.x;          // 0:(0,0) 1:(1,0) 2:(1,1)
    int split = blockIdx.y;
    int bi = (tile == 0) ? 0 : 1;
    int bj = (tile == 2) ? 1 : 0;
    bool diag = (bi == bj);

    const int8_t* Ag = g_q + (size_t)(bi * 128) * DD;
    const int8_t* Bg = g_q + (size_t)(bj * 128) * DD;
    uint32_t offB = diag ? OFF_A : OFF_B;

    int c_lo = (NCHUNKS_TOT * split) / NSPLIT;
    int c_hi = (NCHUNKS_TOT * (split + 1)) / NSPLIT;
    int nch  = c_hi - c_lo;

    // per-thread fixed load slot
    int lrow = t >> 1;               // 0..127 (2 threads per row)
    int lcc0 = (t & 1) * 4;          // 16B lanes 0-3 or 4-7
    const int8_t* asrc = Ag + (size_t)lrow * DD;
    const int8_t* bsrc = Bg + (size_t)lrow * DD;

    auto issue_load = [&](int c, int buf) {
        uint32_t dstb = sbase + buf * STAGE_BYTES;
        int k0 = c * BKCI;
        #pragma unroll
        for (int cc = 0; cc < 4; cc++)
            cp16(dstb + OFF_A + sw128(lrow * 128 + (lcc0 + cc) * 16),
                 asrc + k0 + (lcc0 + cc) * 16);
        if (!diag) {
            #pragma unroll
            for (int cc = 0; cc < 4; cc++)
                cp16(dstb + OFF_B + sw128(lrow * 128 + (lcc0 + cc) * 16),
                     bsrc + k0 + (lcc0 + cc) * 16);
        }
        CP_COMMIT();
    };

    int wr = wid >> 2;               // m half
    int wc = wid & 3;                // n quarter
    int m_base = wr * 64;
    int n_base = wc * 32;

    int acc[4][4][4];
    #pragma unroll
    for (int mi = 0; mi < 4; mi++)
        #pragma unroll
        for (int ni = 0; ni < 4; ni++)
            #pragma unroll
            for (int r = 0; r < 4; r++) acc[mi][ni][r] = 0;

    int l7  = lid & 7;
    int lb8 = (lid >> 3) & 1;
    int lhi = lid >> 4;

    // precomputed ldsm swizzled offsets (kk varies in loop)
    uint32_t a_off[4], b_off[2];
    #pragma unroll
    for (int mi = 0; mi < 4; mi++) {
        int row = m_base + mi * 16 + l7 + lb8 * 8;
        a_off[mi] = row * 128 + lhi * 16;
    }
    #pragma unroll
    for (int nj = 0; nj < 2; nj++) {
        int row = n_base + nj * 16 + l7 + lhi * 8;
        b_off[nj] = row * 128 + lb8 * 16;
    }

    issue_load(c_lo, 0);
    if (1 < nch) issue_load(c_lo + 1, 1);

    for (int ci = 0; ci < nch; ci++) {
        int buf = ci % NSTAGE;
        if (ci + 1 < nch) CP_WAIT(1); else CP_WAIT(0);
        __syncthreads();
        if (ci + 2 < nch) issue_load(c_lo + ci + 2, (ci + 2) % NSTAGE);

        uint32_t bbA = sbase + buf * STAGE_BYTES + OFF_A;
        uint32_t bbB = sbase + buf * STAGE_BYTES + offB;
        #pragma unroll
        for (int kk = 0; kk < 4; kk++) {       // 4 k32 steps per 128B chunk
            uint32_t a[4][4];
            #pragma unroll
            for (int mi = 0; mi < 4; mi++)
                ldsm4(a[mi][0], a[mi][1], a[mi][2], a[mi][3],
                      bbA + sw128(a_off[mi] + kk * 32));
            uint32_t b[4][2];
            #pragma unroll
            for (int nj = 0; nj < 2; nj++) {
                uint32_t r0, r1, r2, r3;
                ldsm4(r0, r1, r2, r3, bbB + sw128(b_off[nj] + kk * 32));
                b[nj * 2][0] = r0;     b[nj * 2][1] = r1;
                b[nj * 2 + 1][0] = r2; b[nj * 2 + 1][1] = r3;
            }
            #pragma unroll
            for (int mi = 0; mi < 4; mi++)
                #pragma unroll
                for (int ni = 0; ni < 4; ni++)
                    mma_s8(acc[mi][ni], a[mi], b[ni][0], b[ni][1]);
        }
    }
    __syncthreads();

    // epilogue
    int* P = g_part + ((size_t)split * 3 + tile) * BMG * BMG;
    int g  = lid >> 2;
    int tg = lid & 3;
    #pragma unroll
    for (int mi = 0; mi < 4; mi++) {
        int m0 = m_base + mi * 16;
        #pragma unroll
        for (int ni = 0; ni < 4; ni++) {
            int n0 = n_base + ni * 8 + 2 * tg;
            *reinterpret_cast<int2*>(P + (m0 + g) * BMG + n0) =
                make_int2(acc[mi][ni][0], acc[mi][ni][1]);
            *reinterpret_cast<int2*>(P + (m0 + g + 8) * BMG + n0) =
                make_int2(acc[mi][ni][2], acc[mi][ni][3]);
        }
    }
}

// ---------------------------------------------------------------------------
// Kernel 3: exact reduction of s32 partials (in double) -> float Gram.
// ---------------------------------------------------------------------------
__global__ void reduce_kernel() {
    int i = blockIdx.x;
    int j = threadIdx.x;

    int tile, r, c;
    if (i < 128 && j < 128)        { tile = 0; r = i;       c = j; }
    else if (i >= 128 && j < 128)  { tile = 1; r = i - 128; c = j; }
    else if (i >= 128 && j >= 128) { tile = 2; r = i - 128; c = j - 128; }
    else                            { tile = 1; r = j - 128; c = i; }  // mirror

    double sum = 0.0;
    const int* base = g_part + (size_t)tile * BMG * BMG + r * BMG + c;
    for (int s = 0; s < NSPLIT; s++)
        sum += (double)base[(size_t)s * 3 * BMG * BMG];

    g_G[i * BB + j] = (float)(sum * QINV2);
}

// ---------------------------------------------------------------------------
// Kernel 4: per-row pass: sum_j |clip(corr_ij)| and G row sums.
// ---------------------------------------------------------------------------
__global__ void rowpass_kernel() {
    int i = blockIdx.x;
    int j = threadIdx.x;
    __shared__ double redA[BB];
    __shared__ double redG[BB];

    const double dD  = (double)DD;
    const double inv = 1.0 / (dD - 1.0);

    double s_i = g_rowsum[i];
    double s_j = g_rowsum[j];
    double Gij = (j == i) ? g_rowsumsq[i] : (double)g_G[i * BB + j];

    double cov = (Gij - s_i * s_j / dD) * inv;
    double c = fabs(cov / (g_std[i] * g_std[j]));
    if (c > 1.0) c = 1.0;

    redA[j] = c;
    redG[j] = Gij;
    __syncthreads();
    for (int st = 128; st > 0; st >>= 1) {
        if (j < st) { redA[j] += redA[j + st]; redG[j] += redG[j + st]; }
        __syncthreads();
    }
    if (j == 0) { g_f1[i] = redA[0]; g_G1[i] = redG[0]; }
}

// ---------------------------------------------------------------------------
// Kernel 5: combine scalars -> p.
// ---------------------------------------------------------------------------
__global__ void combine_kernel() {
    int i = threadIdx.x;
    __shared__ double red[BB];
    __shared__ unsigned long long shm[BB];

    double q  = g_rowsumsq[i];
    double G1 = g_G1[i];
    unsigned long long mymask = g_rowmask[i];
    shm[i] = mymask;
    __syncthreads();

    for (int st = 128; st > 0; st >>= 1) {
        if (i < st) shm[i] |= shm[i + st];
        __syncthreads();
    }
    int total_u = __popcll(shm[0]);
    int row_u   = __popcll(mymask);

    red[i] = G1; __syncthreads();
    for (int st = 128; st > 0; st >>= 1) {
        if (i < st) red[i] += red[i + st];
        __syncthreads();
    }
    double S = red[0];
    __syncthreads();

    const double dD = (double)DD;
    const double dB = (double)BB;
    double mseD    = q - (2.0 / dB) * G1 + S / (dB * dB);
    double row_mse = mseD / dD;

    red[i] = row_mse; __syncthreads();
    for (int st = 128; st > 0; st >>= 1) {
        if (i < st) red[i] += red[i + st];
        __syncthreads();
    }
    double total_mse = red[0];
    __syncthreads();

    double factor1 = g_f1[i] / dB;
    double f2   = row_mse / total_mse;
    double f3   = (double)row_u / (double)total_u;
    double cand = (1.0 - factor1) * f2 * f3;

    red[i] = cand; __syncthreads();
    for (int st = 128; st > 0; st >>= 1) {
        if (i < st) red[i] = fmax(red[i], red[i + st]);
        __syncthreads();
    }
    if (i == 0) {
        double p = fmax(red[0], 0.0);
        float pf = (float)p;
        g_p = pf;
        g_scale = 1.0f / (1.0f - pf);
    }
}

// ---------------------------------------------------------------------------
// Kernel 6: dropout. out = x * (noise >= p) / (1-p)
// ---------------------------------------------------------------------------
__global__ void dropout_kernel(const float* __restrict__ x,
                               const float* __restrict__ noise,
                               float* __restrict__ out) {
    float p  = g_p;
    float sc = g_scale;
    int idx = blockIdx.x * blockDim.x + threadIdx.x;
    const int n4 = BB * DD / 4;
    if (idx < n4) {
        float4 v  = reinterpret_cast<const float4*>(x)[idx];
        float4 nz = reinterpret_cast<const float4*>(noise)[idx];
        float4 o;
        o.x = (nz.x >= p) ? v.x * sc : 0.f;
        o.y = (nz.y >= p) ? v.y * sc : 0.f;
        o.z = (nz.z >= p) ? v.z * sc : 0.f;
        o.w = (nz.w >= p) ? v.w * sc : 0.f;
        reinterpret_cast<float4*>(out)[idx] = o;
    }
}

extern "C" void kernel_launch(void* const* d_in, const int* in_sizes, int n_in,
                              void* d_out, int out_size) {
    const float* x     = (const float*)d_in[0];
    const float* noise = (const float*)d_in[1];
    float* out = (float*)d_out;

    cudaFuncSetAttribute(gram_imma_kernel,
                         cudaFuncAttributeMaxDynamicSharedMemorySize, GRAM_SMEM);

    noop_kernel<<<1, 32>>>();
    noop_kernel<<<1, 32>>>();
    statsconv_kernel<<<BB, 256>>>(x);
    gram_imma_kernel<<<dim3(3, NSPLIT), 256, GRAM_SMEM>>>();
    reduce_kernel<<<BB, 256>>>();
    rowpass_kernel<<<BB, 256>>>();
    combine_kernel<<<1, BB>>>();
    const int n4 = BB * DD / 4;
    dropout_kernel<<<(n4 + 255) / 256, 256>>>(x, noise, out);
}